// round 9
// baseline (speedup 1.0000x reference)
#include <cuda_runtime.h>
#include <math.h>

#define LDIM     1024
#define NROWS    32768       // B*D = 64*512
#define NBLK     4096        // NROWS / 8 rows-per-block
#define NWORK    32          // last 32 arrivals run the epilogue
#define SLICE    (NROWS / NWORK)   // 1024 rows per worker

// Scratch (allocation-free per harness rules)
__device__ float    g_att[NROWS];
__device__ float2   g_partial[NBLK];
__device__ unsigned g_done = 0;   // monotonic arrival counter (never reset)

__global__ void __launch_bounds__(256)
fused_kernel(const float4* __restrict__ x,
             const float*  __restrict__ fc_w,
             const float*  __restrict__ fc_b,
             const float*  __restrict__ bn_gamma,
             const float*  __restrict__ bn_beta,
             const float*  __restrict__ conv_w,
             const float*  __restrict__ conv_b,
             float* __restrict__ out, int out_size) {
    __shared__ float sw[LDIM];
    __shared__ float s_att[8];
    __shared__ float s_ws[8], s_wq[8];
    __shared__ float s_mi[2];
    __shared__ int   s_slice;

    const int t    = threadIdx.x;
    const int warp = t >> 5;
    const int lane = t & 31;

    // ---- w[l] = sqrt(2/L)*(fc_w0/sqrt2 + sum_{k=1..4} fc_wk*cos(k*ph)),
    //      Chebyshev recurrence: one cosf per element ----
    {
        const float sqrt2L = sqrtf(2.0f / (float)LDIM);
        const float pi = 3.14159265358979323846f;
        float w0 = fc_w[0] * 0.70710678118654752f;
        float w1 = fc_w[1], w2 = fc_w[2], w3 = fc_w[3], w4 = fc_w[4];
#pragma unroll
        for (int j = 0; j < 4; j++) {
            int l = t + j * 256;
            float ph = pi * ((float)l + 0.5f) / (float)LDIM;
            float c1 = cosf(ph);
            float c2 = 2.0f * c1 * c1 - 1.0f;
            float c3 = 2.0f * c1 * c2 - c1;
            float c4 = 2.0f * c1 * c3 - c2;
            sw[l] = sqrt2L * (w0 + w1 * c1 + w2 * c2 + w3 * c3 + w4 * c4);
        }
    }
    __syncthreads();

    // ---- dot: one warp per row, 8 rows per block ----
    int row = blockIdx.x * 8 + warp;
    const float4* xr = x + (size_t)row * (LDIM / 4);
    const float4* wr = (const float4*)sw;

    float acc = 0.0f;
#pragma unroll
    for (int j = 0; j < 8; j++) {
        int idx = j * 32 + lane;
        float4 v = __ldcs(xr + idx);
        float4 w = wr[idx];
        acc += v.x * w.x + v.y * w.y + v.z * w.z + v.w * w.w;
    }
#pragma unroll
    for (int off = 16; off; off >>= 1)
        acc += __shfl_xor_sync(0xffffffffu, acc, off);

    float att = acc + fc_b[0];
    if (lane == 0) {
        g_att[row] = att;
        s_att[warp] = att;
    }
    __syncthreads();

    // ---- publish block partial, arrive; last NWORK arrivals become workers ----
    if (t == 0) {
        float s = 0.0f, q = 0.0f;
#pragma unroll
        for (int i = 0; i < 8; i++) {
            float v = s_att[i];
            s += v;
            q += v * v;
        }
        g_partial[blockIdx.x] = make_float2(s, q);
        __threadfence();                          // release partial + g_att
        unsigned old = atomicAdd(&g_done, 1u);
        unsigned rank = old % NBLK;               // rank within this generation
        int slice = -1;
        if (rank >= NBLK - NWORK) {
            slice = (int)(rank - (NBLK - NWORK));
            unsigned target = old - rank + NBLK;  // this generation's goal
            unsigned c;
            for (;;) {
                asm volatile("ld.acquire.gpu.u32 %0, [%1];" : "=r"(c) : "l"(&g_done));
                if (c >= target) break;
                __nanosleep(64);
            }
        }
        s_slice = slice;
    }
    __syncthreads();

    int slice = s_slice;
    if (slice < 0) return;                        // non-worker blocks retire

    // ================= EPILOGUE (32 worker blocks, 1024 rows each) ==========
    // Redundant stats reduction: 256 threads x 16 partials, fixed order.
    {
        float s = 0.0f, q = 0.0f;
#pragma unroll
        for (int j = 0; j < NBLK / 256; j++) {
            float2 p = __ldcg(&g_partial[t + j * 256]);
            s += p.x;
            q += p.y;
        }
#pragma unroll
        for (int off = 16; off; off >>= 1) {
            s += __shfl_xor_sync(0xffffffffu, s, off);
            q += __shfl_xor_sync(0xffffffffu, q, off);
        }
        if (lane == 0) { s_ws[warp] = s; s_wq[warp] = q; }
    }
    __syncthreads();
    if (warp == 0 && lane < 8) {
        float ss = s_ws[lane], qq = s_wq[lane];
#pragma unroll
        for (int off = 4; off; off >>= 1) {
            ss += __shfl_xor_sync(0xffu, ss, off);
            qq += __shfl_xor_sync(0xffu, qq, off);
        }
        if (lane == 0) {
            float mean = ss / (float)NROWS;
            float var  = qq / (float)NROWS - mean * mean;
            s_mi[0] = mean;
            s_mi[1] = rsqrtf(var + 1e-5f);
        }
    }
    __syncthreads();

    float mean = s_mi[0], inv = s_mi[1];
    float gmm = bn_gamma[0], bt = bn_beta[0];
    float cw = conv_w[0], cb = conv_b[0];
    int base = slice * SLICE;
#pragma unroll
    for (int j = 0; j < SLICE / 256; j++) {
        int i = base + t + j * 256;
        float a = (__ldcg(&g_att[i]) - mean) * inv * gmm + bt;
        a = 0.5f * a * (1.0f + erff(a * 0.70710678118654752f));
        float z = a * cw + cb;
        float g = 1.0f / (1.0f + expf(-z));
        out[i] = g;
        if (out_size >= 2 * NROWS) out[i + NROWS] = g;
    }
}

// ---------------------------------------------------------------------------
// Inputs (metadata order): x[64,512,1024] f32, fc_w[5], fc_b[1],
//                          bn_gamma[1], bn_beta[1], conv_w[1], conv_b[1]
// Output: (att1, att2) each [B, D, 1] -> 2*32768 f32
// ---------------------------------------------------------------------------
extern "C" void kernel_launch(void* const* d_in, const int* in_sizes, int n_in,
                              void* d_out, int out_size) {
    const float4* x        = (const float4*)d_in[0];
    const float*  fc_w     = (const float*)d_in[1];
    const float*  fc_b     = (const float*)d_in[2];
    const float*  bn_gamma = (const float*)d_in[3];
    const float*  bn_beta  = (const float*)d_in[4];
    const float*  conv_w   = (const float*)d_in[5];
    const float*  conv_b   = (const float*)d_in[6];
    float* out = (float*)d_out;

    fused_kernel<<<NBLK, 256>>>(x, fc_w, fc_b, bn_gamma, bn_beta,
                                conv_w, conv_b, out, out_size);
}

// round 10
// speedup vs baseline: 1.0823x; 1.0823x over previous
#include <cuda_runtime.h>
#include <math.h>

#define LDIM    1024
#define NROWS   32768      // B*D = 64*512
#define NBLK_A  4096       // NROWS / 8 rows-per-block
#define NBLK_B  128        // 128 * 256 = NROWS

// Scratch (allocation-free per harness rules)
__device__ float  g_att[NROWS];
__device__ float2 g_partial[NBLK_A];

// ---------------------------------------------------------------------------
// Kernel A: per-row dot. Loads issued FIRST (nothing blocks them), then the
// Chebyshev w-build runs in their DRAM-latency shadow, then LDS+FMA+reduce.
// 4096 blocks x 256 threads; one warp per 1024-float row.
// ---------------------------------------------------------------------------
__global__ void __launch_bounds__(256) dot_kernel(const float4* __restrict__ x,
                                                  const float* __restrict__ fc_w,
                                                  const float* __restrict__ fc_b) {
    __shared__ float sw[LDIM];
    __shared__ float s_att[8];
    const int t    = threadIdx.x;
    const int warp = t >> 5;
    const int lane = t & 31;

    // ---- issue this warp's 8 x-loads immediately ----
    const int row = blockIdx.x * 8 + warp;
    const float4* xr = x + (size_t)row * (LDIM / 4);
    float4 v0 = __ldcs(xr + 0 * 32 + lane);
    float4 v1 = __ldcs(xr + 1 * 32 + lane);
    float4 v2 = __ldcs(xr + 2 * 32 + lane);
    float4 v3 = __ldcs(xr + 3 * 32 + lane);
    float4 v4 = __ldcs(xr + 4 * 32 + lane);
    float4 v5 = __ldcs(xr + 5 * 32 + lane);
    float4 v6 = __ldcs(xr + 6 * 32 + lane);
    float4 v7 = __ldcs(xr + 7 * 32 + lane);

    // ---- w-build hidden under the in-flight loads:
    //      w[l] = sqrt(2/L)*(fc_w0/sqrt2 + sum_{k=1..4} fc_wk*cos(k*ph)) ----
    {
        const float sqrt2L = sqrtf(2.0f / (float)LDIM);
        const float pi = 3.14159265358979323846f;
        float w0 = fc_w[0] * 0.70710678118654752f;
        float w1 = fc_w[1], w2 = fc_w[2], w3 = fc_w[3], w4 = fc_w[4];
#pragma unroll
        for (int j = 0; j < 4; j++) {
            int l = t + j * 256;
            float ph = pi * ((float)l + 0.5f) / (float)LDIM;
            float c1 = cosf(ph);
            float c2 = 2.0f * c1 * c1 - 1.0f;
            float c3 = 2.0f * c1 * c2 - c1;
            float c4 = 2.0f * c1 * c3 - c2;
            sw[l] = sqrt2L * (w0 + w1 * c1 + w2 * c2 + w3 * c3 + w4 * c4);
        }
    }
    __syncthreads();

    // ---- consume loads ----
    const float4* wr = (const float4*)sw;
    float acc = 0.0f;
    {
        float4 w;
        w = wr[0 * 32 + lane]; acc += v0.x*w.x + v0.y*w.y + v0.z*w.z + v0.w*w.w;
        w = wr[1 * 32 + lane]; acc += v1.x*w.x + v1.y*w.y + v1.z*w.z + v1.w*w.w;
        w = wr[2 * 32 + lane]; acc += v2.x*w.x + v2.y*w.y + v2.z*w.z + v2.w*w.w;
        w = wr[3 * 32 + lane]; acc += v3.x*w.x + v3.y*w.y + v3.z*w.z + v3.w*w.w;
        w = wr[4 * 32 + lane]; acc += v4.x*w.x + v4.y*w.y + v4.z*w.z + v4.w*w.w;
        w = wr[5 * 32 + lane]; acc += v5.x*w.x + v5.y*w.y + v5.z*w.z + v5.w*w.w;
        w = wr[6 * 32 + lane]; acc += v6.x*w.x + v6.y*w.y + v6.z*w.z + v6.w*w.w;
        w = wr[7 * 32 + lane]; acc += v7.x*w.x + v7.y*w.y + v7.z*w.z + v7.w*w.w;
    }
#pragma unroll
    for (int off = 16; off; off >>= 1)
        acc += __shfl_xor_sync(0xffffffffu, acc, off);

    float att = acc + fc_b[0];
    if (lane == 0) {
        g_att[row] = att;
        s_att[warp] = att;
    }
    __syncthreads();

    if (t == 0) {
        float s = 0.0f, q = 0.0f;
#pragma unroll
        for (int i = 0; i < 8; i++) {
            float v = s_att[i];
            s += v;
            q += v * v;
        }
        g_partial[blockIdx.x] = make_float2(s, q);
    }
}

// ---------------------------------------------------------------------------
// Kernel B: redundant per-block stats reduce (warp-parallel, 2 syncs)
// + BN + exact GELU + sigmoid gate. 128 blocks x 256 threads, 1 row/thread.
// ---------------------------------------------------------------------------
__global__ void __launch_bounds__(256) epilogue_kernel(float* __restrict__ out,
                                                       const float* __restrict__ bn_gamma,
                                                       const float* __restrict__ bn_beta,
                                                       const float* __restrict__ conv_w,
                                                       const float* __restrict__ conv_b,
                                                       int out_size) {
    __shared__ float s_ws[8], s_wq[8];
    __shared__ float s_mi[2];
    int t    = threadIdx.x;
    int warp = t >> 5;
    int lane = t & 31;

    // 256 threads x 16 partials each, fixed order -> deterministic.
    float s = 0.0f, q = 0.0f;
#pragma unroll
    for (int j = 0; j < NBLK_A / 256; j++) {
        float2 p = __ldcg(&g_partial[t + j * 256]);
        s += p.x;
        q += p.y;
    }
#pragma unroll
    for (int off = 16; off; off >>= 1) {
        s += __shfl_xor_sync(0xffffffffu, s, off);
        q += __shfl_xor_sync(0xffffffffu, q, off);
    }
    if (lane == 0) { s_ws[warp] = s; s_wq[warp] = q; }
    __syncthreads();
    if (warp == 0 && lane < 8) {
        float ss = s_ws[lane], qq = s_wq[lane];
#pragma unroll
        for (int off = 4; off; off >>= 1) {
            ss += __shfl_xor_sync(0xffu, ss, off);
            qq += __shfl_xor_sync(0xffu, qq, off);
        }
        if (lane == 0) {
            float mean = ss / (float)NROWS;
            float var  = qq / (float)NROWS - mean * mean;
            s_mi[0] = mean;
            s_mi[1] = rsqrtf(var + 1e-5f);
        }
    }
    __syncthreads();

    int i = blockIdx.x * 256 + t;       // 128*256 == NROWS
    float a = (__ldcg(&g_att[i]) - s_mi[0]) * s_mi[1] * bn_gamma[0] + bn_beta[0];
    a = 0.5f * a * (1.0f + erff(a * 0.70710678118654752f));
    float z = a * conv_w[0] + conv_b[0];
    float g = 1.0f / (1.0f + expf(-z));
    out[i] = g;
    if (out_size >= 2 * NROWS) out[i + NROWS] = g;
}

// ---------------------------------------------------------------------------
// Inputs (metadata order): x[64,512,1024] f32, fc_w[5], fc_b[1],
//                          bn_gamma[1], bn_beta[1], conv_w[1], conv_b[1]
// Output: (att1, att2) each [B, D, 1] -> 2*32768 f32
// ---------------------------------------------------------------------------
extern "C" void kernel_launch(void* const* d_in, const int* in_sizes, int n_in,
                              void* d_out, int out_size) {
    const float4* x        = (const float4*)d_in[0];
    const float*  fc_w     = (const float*)d_in[1];
    const float*  fc_b     = (const float*)d_in[2];
    const float*  bn_gamma = (const float*)d_in[3];
    const float*  bn_beta  = (const float*)d_in[4];
    const float*  conv_w   = (const float*)d_in[5];
    const float*  conv_b   = (const float*)d_in[6];
    float* out = (float*)d_out;

    dot_kernel<<<NBLK_A, 256>>>(x, fc_w, fc_b);
    epilogue_kernel<<<NBLK_B, 256>>>(out, bn_gamma, bn_beta, conv_w, conv_b, out_size);
}

// round 11
// speedup vs baseline: 1.1361x; 1.0497x over previous
#include <cuda_runtime.h>
#include <math.h>

#define LDIM    1024
#define NROWS   32768      // B*D = 64*512
#define NBLK_A  4096       // NROWS / 8 rows-per-block
#define NBLK_B  128        // 128 * 256 = NROWS

// Scratch (allocation-free per harness rules)
__device__ float  g_att[NROWS];
__device__ float2 g_partial[NBLK_A];

// ---------------------------------------------------------------------------
// Kernel A: per-row dot. Loads issued FIRST, Chebyshev w-build hidden in their
// DRAM-latency shadow, then LDS+FMA+reduce. Fires the PDL trigger as soon as
// the block's results are published so the epilogue can begin launching.
// ---------------------------------------------------------------------------
__global__ void __launch_bounds__(256) dot_kernel(const float4* __restrict__ x,
                                                  const float* __restrict__ fc_w,
                                                  const float* __restrict__ fc_b) {
    __shared__ float sw[LDIM];
    __shared__ float s_att[8];
    const int t    = threadIdx.x;
    const int warp = t >> 5;
    const int lane = t & 31;

    // ---- issue this warp's 8 x-loads immediately ----
    const int row = blockIdx.x * 8 + warp;
    const float4* xr = x + (size_t)row * (LDIM / 4);
    float4 v0 = __ldcs(xr + 0 * 32 + lane);
    float4 v1 = __ldcs(xr + 1 * 32 + lane);
    float4 v2 = __ldcs(xr + 2 * 32 + lane);
    float4 v3 = __ldcs(xr + 3 * 32 + lane);
    float4 v4 = __ldcs(xr + 4 * 32 + lane);
    float4 v5 = __ldcs(xr + 5 * 32 + lane);
    float4 v6 = __ldcs(xr + 6 * 32 + lane);
    float4 v7 = __ldcs(xr + 7 * 32 + lane);

    // ---- w-build hidden under the in-flight loads ----
    {
        const float sqrt2L = sqrtf(2.0f / (float)LDIM);
        const float pi = 3.14159265358979323846f;
        float w0 = fc_w[0] * 0.70710678118654752f;
        float w1 = fc_w[1], w2 = fc_w[2], w3 = fc_w[3], w4 = fc_w[4];
#pragma unroll
        for (int j = 0; j < 4; j++) {
            int l = t + j * 256;
            float ph = pi * ((float)l + 0.5f) / (float)LDIM;
            float c1 = cosf(ph);
            float c2 = 2.0f * c1 * c1 - 1.0f;
            float c3 = 2.0f * c1 * c2 - c1;
            float c4 = 2.0f * c1 * c3 - c2;
            sw[l] = sqrt2L * (w0 + w1 * c1 + w2 * c2 + w3 * c3 + w4 * c4);
        }
    }
    __syncthreads();

    // ---- consume loads ----
    const float4* wr = (const float4*)sw;
    float acc = 0.0f;
    {
        float4 w;
        w = wr[0 * 32 + lane]; acc += v0.x*w.x + v0.y*w.y + v0.z*w.z + v0.w*w.w;
        w = wr[1 * 32 + lane]; acc += v1.x*w.x + v1.y*w.y + v1.z*w.z + v1.w*w.w;
        w = wr[2 * 32 + lane]; acc += v2.x*w.x + v2.y*w.y + v2.z*w.z + v2.w*w.w;
        w = wr[3 * 32 + lane]; acc += v3.x*w.x + v3.y*w.y + v3.z*w.z + v3.w*w.w;
        w = wr[4 * 32 + lane]; acc += v4.x*w.x + v4.y*w.y + v4.z*w.z + v4.w*w.w;
        w = wr[5 * 32 + lane]; acc += v5.x*w.x + v5.y*w.y + v5.z*w.z + v5.w*w.w;
        w = wr[6 * 32 + lane]; acc += v6.x*w.x + v6.y*w.y + v6.z*w.z + v6.w*w.w;
        w = wr[7 * 32 + lane]; acc += v7.x*w.x + v7.y*w.y + v7.z*w.z + v7.w*w.w;
    }
#pragma unroll
    for (int off = 16; off; off >>= 1)
        acc += __shfl_xor_sync(0xffffffffu, acc, off);

    float att = acc + fc_b[0];
    if (lane == 0) {
        g_att[row] = att;
        s_att[warp] = att;
    }
    __syncthreads();

    if (t == 0) {
        float s = 0.0f, q = 0.0f;
#pragma unroll
        for (int i = 0; i < 8; i++) {
            float v = s_att[i];
            s += v;
            q += v * v;
        }
        g_partial[blockIdx.x] = make_float2(s, q);
    }
    // Fire PDL trigger: this block's outputs are published.
    cudaTriggerProgrammaticLaunchCompletion();
}

// ---------------------------------------------------------------------------
// Kernel B (PDL secondary): waits on the primary's completion trigger, then
// redundant per-block stats reduce + BN + exact GELU + sigmoid gate.
// 128 blocks x 256 threads, 1 row/thread.
// ---------------------------------------------------------------------------
__global__ void __launch_bounds__(256) epilogue_kernel(float* __restrict__ out,
                                                       const float* __restrict__ bn_gamma,
                                                       const float* __restrict__ bn_beta,
                                                       const float* __restrict__ conv_w,
                                                       const float* __restrict__ conv_b,
                                                       int out_size) {
    __shared__ float s_ws[8], s_wq[8];
    __shared__ float s_mi[2];
    int t    = threadIdx.x;
    int warp = t >> 5;
    int lane = t & 31;

    // Prefetch the scalar params (independent of primary's output) while
    // waiting, then block until the primary grid's writes are visible.
    float gmm = bn_gamma[0], bt = bn_beta[0];
    float cw = conv_w[0], cb = conv_b[0];
    cudaGridDependencySynchronize();

    // 256 threads x 16 partials each, fixed order -> deterministic.
    float s = 0.0f, q = 0.0f;
#pragma unroll
    for (int j = 0; j < NBLK_A / 256; j++) {
        float2 p = __ldcg(&g_partial[t + j * 256]);
        s += p.x;
        q += p.y;
    }
#pragma unroll
    for (int off = 16; off; off >>= 1) {
        s += __shfl_xor_sync(0xffffffffu, s, off);
        q += __shfl_xor_sync(0xffffffffu, q, off);
    }
    if (lane == 0) { s_ws[warp] = s; s_wq[warp] = q; }
    __syncthreads();
    if (warp == 0 && lane < 8) {
        float ss = s_ws[lane], qq = s_wq[lane];
#pragma unroll
        for (int off = 4; off; off >>= 1) {
            ss += __shfl_xor_sync(0xffu, ss, off);
            qq += __shfl_xor_sync(0xffu, qq, off);
        }
        if (lane == 0) {
            float mean = ss / (float)NROWS;
            float var  = qq / (float)NROWS - mean * mean;
            s_mi[0] = mean;
            s_mi[1] = rsqrtf(var + 1e-5f);
        }
    }
    __syncthreads();

    int i = blockIdx.x * 256 + t;       // 128*256 == NROWS
    float a = (__ldcg(&g_att[i]) - s_mi[0]) * s_mi[1] * gmm + bt;
    a = 0.5f * a * (1.0f + erff(a * 0.70710678118654752f));
    float z = a * cw + cb;
    float g = 1.0f / (1.0f + expf(-z));
    out[i] = g;
    if (out_size >= 2 * NROWS) out[i + NROWS] = g;
}

// ---------------------------------------------------------------------------
// Inputs (metadata order): x[64,512,1024] f32, fc_w[5], fc_b[1],
//                          bn_gamma[1], bn_beta[1], conv_w[1], conv_b[1]
// Output: (att1, att2) each [B, D, 1] -> 2*32768 f32
// ---------------------------------------------------------------------------
extern "C" void kernel_launch(void* const* d_in, const int* in_sizes, int n_in,
                              void* d_out, int out_size) {
    const float4* x        = (const float4*)d_in[0];
    const float*  fc_w     = (const float*)d_in[1];
    const float*  fc_b     = (const float*)d_in[2];
    const float*  bn_gamma = (const float*)d_in[3];
    const float*  bn_beta  = (const float*)d_in[4];
    const float*  conv_w   = (const float*)d_in[5];
    const float*  conv_b   = (const float*)d_in[6];
    float* out = (float*)d_out;

    dot_kernel<<<NBLK_A, 256>>>(x, fc_w, fc_b);

    // Epilogue as PDL secondary: launch overlaps the dot kernel's tail.
    cudaLaunchConfig_t cfg = {};
    cfg.gridDim  = dim3(NBLK_B, 1, 1);
    cfg.blockDim = dim3(256, 1, 1);
    cfg.dynamicSmemBytes = 0;
    cfg.stream = 0;
    cudaLaunchAttribute attrs[1];
    attrs[0].id = cudaLaunchAttributeProgrammaticStreamSerialization;
    attrs[0].val.programmaticStreamSerializationAllowed = 1;
    cfg.attrs = attrs;
    cfg.numAttrs = 1;
    cudaLaunchKernelEx(&cfg, epilogue_kernel, out, bn_gamma, bn_beta,
                       conv_w, conv_b, out_size);
}

// round 12
// speedup vs baseline: 1.1525x; 1.0144x over previous
#include <cuda_runtime.h>
#include <math.h>

#define LDIM    1024
#define NROWS   32768      // B*D = 64*512
#define NBLK_A  4096       // NROWS / 8 rows-per-block
#define NBLK_B  128        // 128 * 256 = NROWS

#define SCALE_S 4294967296.0     // 2^32 for sum
#define SCALE_Q 268435456.0      // 2^28 for sumsq

// Scratch (allocation-free per harness rules). All counters monotonic, never
// reset: each execution's stats are recovered via parity-indexed snapshots.
__device__ float              g_att[NROWS];
__device__ unsigned long long g_sum = 0, g_sq = 0;       // fixed-point totals
__device__ unsigned long long g_snapsum[2] = {0, 0};     // per-generation snaps
__device__ unsigned long long g_snapsq[2]  = {0, 0};
__device__ unsigned           g_rep = 0;                 // execution counter

// ---------------------------------------------------------------------------
// Kernel A: per-row dot. Loads issued FIRST, Chebyshev w-build hidden in their
// DRAM-latency shadow, then LDS+FMA+reduce. Block stats folded into two
// deterministic fixed-point atomics (exact integer adds, order-independent).
// ---------------------------------------------------------------------------
__global__ void __launch_bounds__(256) dot_kernel(const float4* __restrict__ x,
                                                  const float* __restrict__ fc_w,
                                                  const float* __restrict__ fc_b) {
    __shared__ float sw[LDIM];
    __shared__ float s_att[8];
    const int t    = threadIdx.x;
    const int warp = t >> 5;
    const int lane = t & 31;

    if (blockIdx.x == 0 && t == 0) atomicAdd(&g_rep, 1u);   // generation tick

    // ---- issue this warp's 8 x-loads immediately ----
    const int row = blockIdx.x * 8 + warp;
    const float4* xr = x + (size_t)row * (LDIM / 4);
    float4 v0 = __ldcs(xr + 0 * 32 + lane);
    float4 v1 = __ldcs(xr + 1 * 32 + lane);
    float4 v2 = __ldcs(xr + 2 * 32 + lane);
    float4 v3 = __ldcs(xr + 3 * 32 + lane);
    float4 v4 = __ldcs(xr + 4 * 32 + lane);
    float4 v5 = __ldcs(xr + 5 * 32 + lane);
    float4 v6 = __ldcs(xr + 6 * 32 + lane);
    float4 v7 = __ldcs(xr + 7 * 32 + lane);

    // ---- w-build hidden under the in-flight loads ----
    {
        const float sqrt2L = sqrtf(2.0f / (float)LDIM);
        const float pi = 3.14159265358979323846f;
        float w0 = fc_w[0] * 0.70710678118654752f;
        float w1 = fc_w[1], w2 = fc_w[2], w3 = fc_w[3], w4 = fc_w[4];
#pragma unroll
        for (int j = 0; j < 4; j++) {
            int l = t + j * 256;
            float ph = pi * ((float)l + 0.5f) / (float)LDIM;
            float c1 = cosf(ph);
            float c2 = 2.0f * c1 * c1 - 1.0f;
            float c3 = 2.0f * c1 * c2 - c1;
            float c4 = 2.0f * c1 * c3 - c2;
            sw[l] = sqrt2L * (w0 + w1 * c1 + w2 * c2 + w3 * c3 + w4 * c4);
        }
    }
    __syncthreads();

    // ---- consume loads ----
    const float4* wr = (const float4*)sw;
    float acc = 0.0f;
    {
        float4 w;
        w = wr[0 * 32 + lane]; acc += v0.x*w.x + v0.y*w.y + v0.z*w.z + v0.w*w.w;
        w = wr[1 * 32 + lane]; acc += v1.x*w.x + v1.y*w.y + v1.z*w.z + v1.w*w.w;
        w = wr[2 * 32 + lane]; acc += v2.x*w.x + v2.y*w.y + v2.z*w.z + v2.w*w.w;
        w = wr[3 * 32 + lane]; acc += v3.x*w.x + v3.y*w.y + v3.z*w.z + v3.w*w.w;
        w = wr[4 * 32 + lane]; acc += v4.x*w.x + v4.y*w.y + v4.z*w.z + v4.w*w.w;
        w = wr[5 * 32 + lane]; acc += v5.x*w.x + v5.y*w.y + v5.z*w.z + v5.w*w.w;
        w = wr[6 * 32 + lane]; acc += v6.x*w.x + v6.y*w.y + v6.z*w.z + v6.w*w.w;
        w = wr[7 * 32 + lane]; acc += v7.x*w.x + v7.y*w.y + v7.z*w.z + v7.w*w.w;
    }
#pragma unroll
    for (int off = 16; off; off >>= 1)
        acc += __shfl_xor_sync(0xffffffffu, acc, off);

    float att = acc + fc_b[0];
    if (lane == 0) {
        g_att[row] = att;
        s_att[warp] = att;
    }
    __syncthreads();

    if (t == 0) {
        float s = 0.0f, q = 0.0f;
#pragma unroll
        for (int i = 0; i < 8; i++) {
            float v = s_att[i];
            s += v;
            q += v * v;
        }
        // Exact, order-independent accumulation: fixed-point integer atomics.
        long long is = llrint((double)s * SCALE_S);
        long long iq = llrint((double)q * SCALE_Q);
        atomicAdd(&g_sum, (unsigned long long)is);
        atomicAdd(&g_sq,  (unsigned long long)iq);
    }
    cudaTriggerProgrammaticLaunchCompletion();
}

// ---------------------------------------------------------------------------
// Kernel B (PDL secondary): no reductions, no __syncthreads. Post-gridsync
// critical path = 3 scalar loads (parallel with the row load) + ~10 flops.
// ---------------------------------------------------------------------------
__global__ void __launch_bounds__(256) epilogue_kernel(float* __restrict__ out,
                                                       const float* __restrict__ bn_gamma,
                                                       const float* __restrict__ bn_beta,
                                                       const float* __restrict__ conv_w,
                                                       const float* __restrict__ conv_b,
                                                       int out_size) {
    const int t = threadIdx.x;
    const int i = blockIdx.x * 256 + t;        // 128*256 == NROWS

    // Prefetch scalar params (independent of primary) while waiting.
    float gmm = bn_gamma[0], bt = bn_beta[0];
    float cw = conv_w[0], cb = conv_b[0];
    cudaGridDependencySynchronize();

    // All loads below are independent -> issued together, one latency.
    float av = __ldcg(&g_att[i]);
    unsigned long long ts = __ldcg(&g_sum);
    unsigned long long tq = __ldcg(&g_sq);
    unsigned gen = __ldcg(&g_rep);

    unsigned long long ps = __ldcg(&g_snapsum[(gen - 1u) & 1u]);
    unsigned long long pq = __ldcg(&g_snapsq[(gen - 1u) & 1u]);

    double dsum = (double)(long long)(ts - ps) * (1.0 / SCALE_S);
    double dsq  = (double)(long long)(tq - pq) * (1.0 / SCALE_Q);
    float mean = (float)(dsum / (double)NROWS);
    float var  = (float)(dsq  / (double)NROWS) - mean * mean;
    float inv  = rsqrtf(var + 1e-5f);

    float a = (av - mean) * inv * gmm + bt;
    a = 0.5f * a * (1.0f + erff(a * 0.70710678118654752f));
    float z = a * cw + cb;
    float g = 1.0f / (1.0f + expf(-z));
    out[i] = g;
    if (out_size >= 2 * NROWS) out[i + NROWS] = g;

    // Publish this generation's snapshot for the NEXT execution (other parity
    // slot than the one read above -> no intra-execution conflict).
    if (blockIdx.x == 0 && t == 0) {
        g_snapsum[gen & 1u] = ts;
        g_snapsq[gen & 1u]  = tq;
    }
}

// ---------------------------------------------------------------------------
// Inputs (metadata order): x[64,512,1024] f32, fc_w[5], fc_b[1],
//                          bn_gamma[1], bn_beta[1], conv_w[1], conv_b[1]
// Output: (att1, att2) each [B, D, 1] -> 2*32768 f32
// ---------------------------------------------------------------------------
extern "C" void kernel_launch(void* const* d_in, const int* in_sizes, int n_in,
                              void* d_out, int out_size) {
    const float4* x        = (const float4*)d_in[0];
    const float*  fc_w     = (const float*)d_in[1];
    const float*  fc_b     = (const float*)d_in[2];
    const float*  bn_gamma = (const float*)d_in[3];
    const float*  bn_beta  = (const float*)d_in[4];
    const float*  conv_w   = (const float*)d_in[5];
    const float*  conv_b   = (const float*)d_in[6];
    float* out = (float*)d_out;

    dot_kernel<<<NBLK_A, 256>>>(x, fc_w, fc_b);

    cudaLaunchConfig_t cfg = {};
    cfg.gridDim  = dim3(NBLK_B, 1, 1);
    cfg.blockDim = dim3(256, 1, 1);
    cfg.dynamicSmemBytes = 0;
    cfg.stream = 0;
    cudaLaunchAttribute attrs[1];
    attrs[0].id = cudaLaunchAttributeProgrammaticStreamSerialization;
    attrs[0].val.programmaticStreamSerializationAllowed = 1;
    cfg.attrs = attrs;
    cfg.numAttrs = 1;
    cudaLaunchKernelEx(&cfg, epilogue_kernel, out, bn_gamma, bn_beta,
                       conv_w, conv_b, out_size);
}